// round 12
// baseline (speedup 1.0000x reference)
#include <cuda_runtime.h>
#include <cuda_fp16.h>
#include <cstdint>

// ============================================================================
// Problem dims
// ============================================================================
#define B_DIM 4
#define S_DIM 4096
#define D_DIM 1024
#define M_TOT (B_DIM * S_DIM)   // 16384
#define NCH 256
#define CHL (S_DIM / NCH)       // 16

// ============================================================================
// Device scratch (allocation-free rule -> static __device__ arrays)
// ============================================================================
__device__ __align__(128) __half g_xh[M_TOT * D_DIM];     // 32 MB (x as fp16)
__device__ __align__(128) __half g_w[3][D_DIM * D_DIM];   // 6 MB  (Wg,Wv,Wd fp16)
// interleaved (a, xs) pairs, one __half2 per (m, d)
__device__ __align__(128) __half2 g_AX[M_TOT * D_DIM];    // 64 MB
// transposed aggregate layout: [channel][chunk], channel = b*1024 + d
__device__ __align__(128) float g_Aprod[B_DIM * D_DIM * NCH];   // 4 MB
__device__ __align__(128) float g_Hend [B_DIM * D_DIM * NCH];   // 4 MB
__device__ __align__(128) float g_Hin  [B_DIM * D_DIM * NCH];   // 4 MB

// ============================================================================
// PTX helpers (sm_80-level features: mma.sync + cp.async + ldmatrix)
// ============================================================================
__device__ __forceinline__ uint32_t smem_to_u32(const void* p) {
    uint32_t a;
    asm("{ .reg .u64 t; cvta.to.shared.u64 t, %1; cvt.u32.u64 %0, t; }"
        : "=r"(a) : "l"(p));
    return a;
}

__device__ __forceinline__ void cp16(uint32_t dst, const void* src) {
    asm volatile("cp.async.cg.shared.global [%0], [%1], 16;"
                 :: "r"(dst), "l"(src) : "memory");
}
__device__ __forceinline__ void cp_commit() {
    asm volatile("cp.async.commit_group;" ::: "memory");
}

__device__ __forceinline__ void ldsm4(uint32_t* r, uint32_t addr) {
    asm volatile("ldmatrix.sync.aligned.m8n8.x4.shared.b16 {%0,%1,%2,%3}, [%4];"
                 : "=r"(r[0]), "=r"(r[1]), "=r"(r[2]), "=r"(r[3]) : "r"(addr));
}

// D += A * B  (m16n8k16, fp16 in, f32 accum, A row-major, B col-major)
__device__ __forceinline__ void mma16816(float* c, const uint32_t* a, const uint32_t* b) {
    asm volatile(
        "mma.sync.aligned.m16n8k16.row.col.f32.f16.f16.f32 "
        "{%0,%1,%2,%3}, {%4,%5,%6,%7}, {%8,%9}, {%0,%1,%2,%3};"
        : "+f"(c[0]), "+f"(c[1]), "+f"(c[2]), "+f"(c[3])
        : "r"(a[0]), "r"(a[1]), "r"(a[2]), "r"(a[3]), "r"(b[0]), "r"(b[1]));
}

// ============================================================================
// Kernel 1: fused fp32 -> fp16 conversion for x and Wg/Wv/Wd
// ============================================================================
#define X_F4   (M_TOT * D_DIM / 4)          // 4194304 float4s
#define W_F4   (D_DIM * D_DIM / 4)          // 262144 per matrix
#define CVT_F4 (X_F4 + 3 * W_F4)            // 4980736

__global__ void convert_kernel(const float* __restrict__ x,
                               const float* __restrict__ Wg,
                               const float* __restrict__ Wv,
                               const float* __restrict__ Wd) {
    int gid = blockIdx.x * blockDim.x + threadIdx.x;
    const float* src;
    uint2* dst;
    int r;
    if (gid < X_F4) {
        src = x; dst = (uint2*)g_xh; r = gid;
    } else {
        int t = gid - X_F4;
        int which = t / W_F4;
        r = t - which * W_F4;
        src = (which == 0) ? Wg : (which == 1) ? Wv : Wd;
        dst = (uint2*)g_w[which];
    }
    float4 v = ((const float4*)src)[r];
    union { __half h[4]; uint2 u; } hv;
    hv.h[0] = __float2half_rn(v.x);
    hv.h[1] = __float2half_rn(v.y);
    hv.h[2] = __float2half_rn(v.z);
    hv.h[3] = __float2half_rn(v.w);
    dst[r] = hv.u;
}

// ============================================================================
// Kernel 2: fused triple GEMM (fp16) + gate epilogue + chunk aggregates
//   CTA tile: M=256, N=64, K in BK=64 chunks, 3-stage cp.async pipeline
//   (prefetch distance 2, ONE __syncthreads per chunk).
//   512 threads, 16 warps = 8(M) x 2(N); warp tile 32x32 per output.
//   Epilogue: half2 (a,xs) -> g_AX; chunk aggregates (16 local chunks of 16)
//   computed from the QUANTIZED values so the parallel scan is consistent.
// ============================================================================
#define BK 64
#define KCHUNKS 16
#define NSTAGE 3
#define TSTRIDE_B 144                       // 64 fp16 + 8 pad, in bytes
#define XT_BYTES (256 * TSTRIDE_B)          // 36864
#define WT_BYTES (64 * TSTRIDE_B)           // 9216
#define STAGE_BYTES (XT_BYTES + 3 * WT_BYTES)       // 64512
#define GEMM_SMEM (NSTAGE * STAGE_BYTES)            // 193536

__device__ __forceinline__ void stage_load(uint32_t sbase, int m0, int n0,
                                           int k0, int tid) {
    // x tile: 256 rows x 64 fp16 (8 x 16B per row) = 2048 cp16 ops
    #pragma unroll
    for (int it = 0; it < 4; it++) {
        int idx = tid + it * 512;            // 0..2047
        int row = idx >> 3, c16 = idx & 7;
        cp16(sbase + row * TSTRIDE_B + c16 * 16,
             g_xh + (size_t)(m0 + row) * 1024 + k0 + c16 * 8);
    }
    // 3 W tiles: 64 rows x 64 fp16 each = 512 cp16 ops each
    #pragma unroll
    for (int w = 0; w < 3; w++) {
        int row = tid >> 3, c16 = tid & 7;
        cp16(sbase + XT_BYTES + w * WT_BYTES + row * TSTRIDE_B + c16 * 16,
             g_w[w] + (size_t)(n0 + row) * 1024 + k0 + c16 * 8);
    }
}

__global__ __launch_bounds__(512, 1)
void gemm3_kernel(const float* __restrict__ bgp,
                  const float* __restrict__ bvp,
                  const float* __restrict__ bdp) {
    extern __shared__ char smem[];
    const uint32_t smem_u = smem_to_u32(smem);
    const int tid  = threadIdx.x;
    const int wid  = tid >> 5;
    const int lane = tid & 31;
    const int gid  = lane >> 2;            // 0..7
    const int tig  = lane & 3;             // 0..3
    const int warp_m = wid >> 1;           // 0..7
    const int warp_n = wid & 1;            // 0..1
    const int m0 = blockIdx.x * 256;
    const int n0 = blockIdx.y * 64;

    // ldmatrix lane-address components
    const int l8   = lane & 7;
    const int q    = lane >> 3;
    const int a_row_off = l8 + (q & 1) * 8;
    const int a_k_off   = (q >> 1) * 16;   // bytes
    const int b_row_off = l8 + (q >> 1) * 8;
    const int b_k_off   = (q & 1) * 16;    // bytes

    float acc[3][2][4][4];                 // [out][mt][nt][frag] = 96 regs
    #pragma unroll
    for (int w = 0; w < 3; w++)
        #pragma unroll
        for (int mt = 0; mt < 2; mt++)
            #pragma unroll
            for (int nt = 0; nt < 4; nt++)
                #pragma unroll
                for (int f = 0; f < 4; f++) acc[w][mt][nt][f] = 0.f;

    // prologue: fill stages 0 and 1
    stage_load(smem_u,               m0, n0, 0,  tid); cp_commit();
    stage_load(smem_u + STAGE_BYTES, m0, n0, BK, tid); cp_commit();

    int sidx = 0;   // buffer index of current stage (stage ch -> ch % 3)
    for (int ch = 0; ch < KCHUNKS; ch++) {
        if (ch + 1 < KCHUNKS)
            asm volatile("cp.async.wait_group 1;" ::: "memory");
        else
            asm volatile("cp.async.wait_group 0;" ::: "memory");
        __syncthreads();   // orders prior-iteration reads before new stores

        if (ch + 2 < KCHUNKS) {
            int pidx = sidx + 2 >= NSTAGE ? sidx + 2 - NSTAGE : sidx + 2;
            stage_load(smem_u + pidx * STAGE_BYTES, m0, n0, (ch + 2) * BK, tid);
            cp_commit();
        }

        const uint32_t sb = smem_u + sidx * STAGE_BYTES;
        #pragma unroll
        for (int ks = 0; ks < 4; ks++) {
            uint32_t ah[2][4];
            #pragma unroll
            for (int mt = 0; mt < 2; mt++) {
                uint32_t addr = sb
                    + (warp_m * 32 + mt * 16 + a_row_off) * TSTRIDE_B
                    + ks * 32 + a_k_off;
                ldsm4(ah[mt], addr);
            }
            #pragma unroll
            for (int w = 0; w < 3; w++) {
                const uint32_t wb = sb + XT_BYTES + w * WT_BYTES;
                uint32_t bfr[4][2];
                #pragma unroll
                for (int p = 0; p < 2; p++) {
                    uint32_t addr = wb
                        + (warp_n * 32 + p * 16 + b_row_off) * TSTRIDE_B
                        + ks * 32 + b_k_off;
                    uint32_t r[4];
                    ldsm4(r, addr);
                    bfr[p * 2    ][0] = r[0]; bfr[p * 2    ][1] = r[1];
                    bfr[p * 2 + 1][0] = r[2]; bfr[p * 2 + 1][1] = r[3];
                }
                #pragma unroll
                for (int mt = 0; mt < 2; mt++)
                    #pragma unroll
                    for (int nt = 0; nt < 4; nt++)
                        mma16816(acc[w][mt][nt], ah[mt], bfr[nt]);
            }
        }
        sidx = sidx + 1 >= NSTAGE ? 0 : sidx + 1;
    }
    __syncthreads();   // all warps done with stage buffers before smem reuse

    // ---- epilogue: quantized half2 (a,xs) to global + smem park (quantized)
    //   smem reuse: sA [256][65] floats, sX [256][65] floats (133120 B)
    float* sA = (float*)smem;
    float* sX = sA + 256 * 65;

    #pragma unroll
    for (int mt = 0; mt < 2; mt++) {
        #pragma unroll
        for (int half = 0; half < 2; half++) {
            const int mloc = warp_m * 32 + mt * 16 + gid + half * 8;
            const int m = m0 + mloc;
            __half2* AXr = g_AX + (size_t)m * 1024;
            #pragma unroll
            for (int nt = 0; nt < 4; nt++) {
                const int nl = warp_n * 32 + nt * 8 + tig * 2;
                const int n = n0 + nl;
                uint2 pk;
                #pragma unroll
                for (int j = 0; j < 2; j++) {
                    const int f = half * 2 + j;
                    float gg = acc[0][mt][nt][f] + __ldg(bgp + n + j);
                    float vv = acc[1][mt][nt][f] + __ldg(bvp + n + j);
                    float dd = acc[2][mt][nt][f] + __ldg(bdp + n + j);
                    float sg = 1.f / (1.f + __expf(-gg));
                    float sd = 1.f / (1.f + __expf(-dd));
                    float a  = 0.001f + 0.998f * sd;
                    float xs = sg * tanhf(vv);
                    __half2 qh = __floats2half2_rn(a, xs);
                    float2 qf = __half22float2(qh);      // quantized values
                    sA[mloc * 65 + nl + j] = qf.x;
                    sX[mloc * 65 + nl + j] = qf.y;
                    ((uint32_t*)&pk)[j] = *(uint32_t*)&qh;
                }
                *(uint2*)(AXr + n) = pk;                 // 8B store, 2 half2
            }
        }
    }
    __syncthreads();

    // ---- chunk aggregates (from quantized values): 16 chunks x 64 columns
    #pragma unroll
    for (int it = 0; it < 2; it++) {
        const int idx = tid + it * 512;   // 0..1023
        const int chunkl = idx >> 6;      // 0..15
        const int nl = idx & 63;
        float h = 0.f, p = 1.f;
        #pragma unroll
        for (int i = 0; i < CHL; i++) {
            const int mloc = chunkl * CHL + i;
            float a  = sA[mloc * 65 + nl];
            float xs = sX[mloc * 65 + nl];
            h = fmaf(a, h, xs);
            p *= a;
        }
        const int b = m0 >> 12;                       // m0 / 4096
        const int chunkg = ((m0 & 4095) >> 4) + chunkl;
        const int c = b * 1024 + n0 + nl;
        g_Aprod[(size_t)c * NCH + chunkg] = p;
        g_Hend [(size_t)c * NCH + chunkg] = h;
    }
}

// ============================================================================
// Kernel 3: combine NCH chunk aggregates per channel.
//   One warp per channel: 8 elements/lane (2 x float4) + warp shuffle scan
//   over the associative op  (A,X) o (A',X') = (A*A', A'*X + X').
// ============================================================================
__global__ void scan_phase2() {
    const int lane = threadIdx.x & 31;
    const int c = blockIdx.x * 8 + (threadIdx.x >> 5);   // channel 0..4095
    const float4* ap = (const float4*)(g_Aprod + (size_t)c * NCH);
    const float4* hp = (const float4*)(g_Hend  + (size_t)c * NCH);
    float4 a0 = ap[2 * lane], a1 = ap[2 * lane + 1];
    float4 h0 = hp[2 * lane], h1 = hp[2 * lane + 1];

    // lane-local totals over 8 chunks
    float TX = h0.x;
    TX = fmaf(a0.y, TX, h0.y);
    TX = fmaf(a0.z, TX, h0.z);
    TX = fmaf(a0.w, TX, h0.w);
    TX = fmaf(a1.x, TX, h1.x);
    TX = fmaf(a1.y, TX, h1.y);
    TX = fmaf(a1.z, TX, h1.z);
    TX = fmaf(a1.w, TX, h1.w);
    float TA = a0.x * a0.y * a0.z * a0.w * a1.x * a1.y * a1.z * a1.w;

    // warp inclusive scan: cur = op(prev, cur)
    #pragma unroll
    for (int d = 1; d < 32; d <<= 1) {
        float pA = __shfl_up_sync(0xFFFFFFFFu, TA, d);
        float pX = __shfl_up_sync(0xFFFFFFFFu, TX, d);
        if (lane >= d) {
            TX = fmaf(TA, pX, TX);
            TA = TA * pA;
        }
    }
    // exclusive
    float eX = __shfl_up_sync(0xFFFFFFFFu, TX, 1);
    if (lane == 0) eX = 0.f;

    // per-chunk carries: Hin_{j+1} = a_j * Hin_j + h_j
    float4 o0, o1;
    o0.x = eX;
    o0.y = fmaf(a0.x, o0.x, h0.x);
    o0.z = fmaf(a0.y, o0.y, h0.y);
    o0.w = fmaf(a0.z, o0.z, h0.z);
    o1.x = fmaf(a0.w, o0.w, h0.w);
    o1.y = fmaf(a1.x, o1.x, h1.x);
    o1.z = fmaf(a1.y, o1.y, h1.y);
    o1.w = fmaf(a1.z, o1.z, h1.z);
    float4* ip = (float4*)(g_Hin + (size_t)c * NCH);
    ip[2 * lane] = o0;
    ip[2 * lane + 1] = o1;
}

// ============================================================================
// Kernel 4: apply — local scan seeded with Hin, 4 channels per thread
//   (one uint4 = 4 half2 (a,xs) pairs in, one float4 out, per time step)
//   grid (4, NCH) = 1024 CTAs -> ~87% occupancy
// ============================================================================
__global__ void scan_apply(float* __restrict__ out) {
    const int c4 = blockIdx.x * 256 + threadIdx.x;   // 0..1023 (channel quad)
    const int b = c4 >> 8;
    const int dbase = (c4 & 255) * 4;
    const int chunk = blockIdx.y;

    float h[4];
    #pragma unroll
    for (int j = 0; j < 4; j++)
        h[j] = g_Hin[(size_t)(b * 1024 + dbase + j) * NCH + chunk];

    size_t off = ((size_t)b * S_DIM + (size_t)chunk * CHL) * 1024 + dbase;
    #pragma unroll
    for (int t = 0; t < CHL; t++) {
        uint4 raw = *(const uint4*)(g_AX + off);
        float4 o;
        #pragma unroll
        for (int j = 0; j < 4; j++) {
            __half2 ax = *(__half2*)(((uint32_t*)&raw) + j);
            float2 axf = __half22float2(ax);
            h[j] = fmaf(axf.x, h[j], axf.y);
            ((float*)&o)[j] = h[j];
        }
        *(float4*)(out + off) = o;
        off += 1024;
    }
}

// ============================================================================
// Launch
// ============================================================================
extern "C" void kernel_launch(void* const* d_in, const int* in_sizes, int n_in,
                              void* d_out, int out_size) {
    const float* x  = (const float*)d_in[0];
    const float* Wg = (const float*)d_in[1];
    const float* bg = (const float*)d_in[2];
    const float* Wv = (const float*)d_in[3];
    const float* bv = (const float*)d_in[4];
    const float* Wd = (const float*)d_in[5];
    const float* bd = (const float*)d_in[6];
    float* out = (float*)d_out;
    (void)in_sizes; (void)n_in; (void)out_size;

    convert_kernel<<<CVT_F4 / 256, 256>>>(x, Wg, Wv, Wd);

    cudaFuncSetAttribute(gemm3_kernel,
                         cudaFuncAttributeMaxDynamicSharedMemorySize, GEMM_SMEM);
    gemm3_kernel<<<dim3(M_TOT / 256, D_DIM / 64), 512, GEMM_SMEM>>>(bg, bv, bd);

    scan_phase2<<<512, 256>>>();
    scan_apply<<<dim3(4, NCH), 256>>>(out);
}